// round 5
// baseline (speedup 1.0000x reference)
#include <cuda_runtime.h>
#include <cstdint>

#define HGT 512
#define WID 512
#define NB 2
#define NCH 64
#define NPTS 131072
#define NMASK 131072

// Scratch via __device__ globals (allocations are forbidden).
__device__ __align__(16) float g_mask[NB * HGT * WID];
__device__ int g_mode[2];   // 0 = int64 rows, 1 = int32 rows, 2 = float32 rows

// ---------------------------------------------------------------------------
// Index-format detection + robust row loader
// ---------------------------------------------------------------------------
__device__ __forceinline__ int detect_mode(const void* p) {
    const unsigned* w = (const unsigned*)p;
    bool hi_zero = true;
#pragma unroll
    for (int k = 0; k < 16; ++k) hi_zero &= (w[2 * k + 1] == 0u);
    if (hi_zero) return 0;                 // int64: hi word of every qword is 0
    bool small = true;
#pragma unroll
    for (int k = 0; k < 16; ++k) small &= (w[k] < 0x10000u);
    return small ? 1 : 2;                  // small raw words -> int32, else float32
}

__global__ void detect_kernel(const void* idx, const void* midx) {
    if (threadIdx.x == 0) g_mode[0] = detect_mode(idx);
    if (threadIdx.x == 1) g_mode[1] = detect_mode(midx);
}

__device__ __forceinline__ void load_row3(const void* p, int i, int mode,
                                          int& b, int& y, int& x) {
    if (mode == 0) {
        const long long* q = (const long long*)p + 3 * (size_t)i;
        b = (int)q[0]; y = (int)q[1]; x = (int)q[2];
    } else if (mode == 1) {
        const int* q = (const int*)p + 3 * (size_t)i;
        b = q[0]; y = q[1]; x = q[2];
    } else {
        const float* q = (const float*)p + 3 * (size_t)i;
        b = (int)q[0]; y = (int)q[1]; x = (int)q[2];
    }
    // Defensive clamps: wrong parse must never produce a wild address.
    b = b < 0 ? 0 : (b > NB - 1 ? NB - 1 : b);
    y = y < 0 ? 0 : (y > HGT - 1 ? HGT - 1 : y);
    x = x < 0 ? 0 : (x > WID - 1 ? WID - 1 : x);
}

// ---------------------------------------------------------------------------
// Kernel 1: zero the dense accumulator (d_out) and the mask grid.
// ---------------------------------------------------------------------------
__global__ void zero_kernel(float4* __restrict__ out4, int n_out4) {
    int i = blockIdx.x * blockDim.x + threadIdx.x;
    float4 z = make_float4(0.f, 0.f, 0.f, 0.f);
    if (i < n_out4) out4[i] = z;
    const int n_mask4 = NB * HGT * WID / 4;
    if (i < n_mask4) reinterpret_cast<float4*>(g_mask)[i] = z;
}

// ---------------------------------------------------------------------------
// Kernel 2: scatter mask_values into the mask grid.
// ---------------------------------------------------------------------------
__global__ void mask_scatter_kernel(const void* __restrict__ mi,
                                    const float* __restrict__ mv) {
    int i = blockIdx.x * blockDim.x + threadIdx.x;
    if (i < NMASK) {
        int b, y, x;
        load_row3(mi, i, g_mode[1], b, y, x);
        atomicAdd(&g_mask[(b * HGT + y) * WID + x], mv[i]);
    }
}

// ---------------------------------------------------------------------------
// Kernel 3: fused per-tap GEMM (128 points x 64 out, K=64) + atomic scatter.
// Block: 256 threads = 16x16; thread (ty,tx) owns 8 rows x 4 cols.
// ---------------------------------------------------------------------------
__global__ __launch_bounds__(256, 2) void conv_scatter_kernel(
    const float* __restrict__ values, const float* __restrict__ kern,
    const void* __restrict__ idx, float* __restrict__ dense) {
    __shared__ float As[128][64];
    __shared__ float Bs[64][64];
    __shared__ int Pb[128], Py[128], Px[128];

    const int tid = threadIdx.x;
    const int m0 = blockIdx.x * 128;
    const int mode = g_mode[0];

    for (int i = tid; i < 128 * 16; i += 256) {
        int m = i >> 4;
        int c = (i & 15) << 2;
        float4 v = *reinterpret_cast<const float4*>(values + (size_t)(m0 + m) * NCH + c);
        *reinterpret_cast<float4*>(&As[m][c]) = v;
    }
    for (int i = tid; i < 128; i += 256) {
        int b, y, x;
        load_row3(idx, m0 + i, mode, b, y, x);
        Pb[i] = b; Py[i] = y; Px[i] = x;
    }

    const int ty = tid >> 4;
    const int tx = tid & 15;

#pragma unroll 1
    for (int tap = 0; tap < 9; ++tap) {
        __syncthreads();
        const float4* bsrc = reinterpret_cast<const float4*>(kern + (size_t)tap * NCH * NCH);
        for (int i = tid; i < 64 * 16; i += 256)
            reinterpret_cast<float4*>(Bs)[i] = bsrc[i];
        __syncthreads();

        float4 acc[8];
#pragma unroll
        for (int i = 0; i < 8; ++i) acc[i] = make_float4(0.f, 0.f, 0.f, 0.f);

#pragma unroll 8
        for (int k = 0; k < 64; ++k) {
            float4 b = *reinterpret_cast<const float4*>(&Bs[k][tx * 4]);
#pragma unroll
            for (int i = 0; i < 8; ++i) {
                float a = As[ty * 8 + i][k];
                acc[i].x = fmaf(a, b.x, acc[i].x);
                acc[i].y = fmaf(a, b.y, acc[i].y);
                acc[i].z = fmaf(a, b.z, acc[i].z);
                acc[i].w = fmaf(a, b.w, acc[i].w);
            }
        }

        const int dy = tap / 3 - 1;
        const int dx = tap % 3 - 1;
#pragma unroll
        for (int i = 0; i < 8; ++i) {
            int m = ty * 8 + i;
            int sy = Py[m] + dy;
            sy = sy < 0 ? 0 : (sy > HGT - 1 ? HGT - 1 : sy);
            int sx = Px[m] + dx;
            sx = sx < 0 ? 0 : (sx > WID - 1 ? WID - 1 : sx);
            float* p = dense + ((((size_t)Pb[m] * HGT + sy) * WID + sx) * NCH) + tx * 4;
            atomicAdd(p + 0, acc[i].x);
            atomicAdd(p + 1, acc[i].y);
            atomicAdd(p + 2, acc[i].z);
            atomicAdd(p + 3, acc[i].w);
        }
    }
}

// ---------------------------------------------------------------------------
// Kernel 4: epilogue  out = (dense + mask*bias) * mask   (in place on d_out)
// ---------------------------------------------------------------------------
__global__ void epilogue_kernel(float4* __restrict__ out4,
                                const float4* __restrict__ bias4) {
    int i = blockIdx.x * blockDim.x + threadIdx.x;
    float m = g_mask[i >> 4];
    float4 d = out4[i];
    float4 bv = __ldg(&bias4[i & 15]);
    d.x = (d.x + m * bv.x) * m;
    d.y = (d.y + m * bv.y) * m;
    d.z = (d.z + m * bv.z) * m;
    d.w = (d.w + m * bv.w) * m;
    out4[i] = d;
}

// ---------------------------------------------------------------------------
extern "C" void kernel_launch(void* const* d_in, const int* in_sizes, int n_in,
                              void* d_out, int out_size) {
    // Identify inputs by element count (robust to metadata ordering).
    const float* values = nullptr;      // 131072*64      = 8388608
    const float* kern = nullptr;        // 3*3*64*64      = 36864
    const float* bias = nullptr;        // 64
    const float* mask_values = nullptr; // 131072
    const void* indices = nullptr;      // 131072*3       = 393216 (or 786432 if counted as i32 pairs)
    const void* mask_indices = nullptr;

    for (int i = 0; i < n_in; ++i) {
        int s = in_sizes[i];
        if (s == 8388608)      values = (const float*)d_in[i];
        else if (s == 36864)   kern = (const float*)d_in[i];
        else if (s == 64)      bias = (const float*)d_in[i];
        else if (s == 131072)  mask_values = (const float*)d_in[i];
        else if (s == 393216 || s == 786432) {
            if (!indices) indices = d_in[i];
            else          mask_indices = d_in[i];
        }
    }
    // Positional fallback (original assumption) if anything is missing.
    if (!values)       values       = (const float*)d_in[0];
    if (!kern)         kern         = (const float*)d_in[1];
    if (!bias)         bias         = (const float*)d_in[2];
    if (!mask_values)  mask_values  = (const float*)d_in[3];
    if (!indices)      indices      = d_in[4];
    if (!mask_indices) mask_indices = d_in[5];

    float* out = (float*)d_out;
    const int n_out4 = NB * HGT * WID * NCH / 4;  // 8388608

    detect_kernel<<<1, 32>>>(indices, mask_indices);
    zero_kernel<<<(n_out4 + 255) / 256, 256>>>((float4*)out, n_out4);
    mask_scatter_kernel<<<(NMASK + 255) / 256, 256>>>(mask_indices, mask_values);
    conv_scatter_kernel<<<NPTS / 128, 256>>>(values, kern, indices, out);
    epilogue_kernel<<<n_out4 / 256, 256>>>((float4*)out, (const float4*)bias);
}

// round 6
// speedup vs baseline: 1.5643x; 1.5643x over previous
#include <cuda_runtime.h>
#include <cstdint>

#define HGT 512
#define WID 512
#define NB 2
#define NCH 64
#define NPTS 131072
#define NMASK 131072

// Scratch via __device__ globals (allocations are forbidden).
__device__ __align__(16) float g_mask[NB * HGT * WID];
__device__ int g_mode[2];   // 0 = int64 rows, 1 = int32 rows, 2 = float32 rows

// ---------------------------------------------------------------------------
// Index-format detection + robust row loader
// ---------------------------------------------------------------------------
__device__ __forceinline__ int detect_mode(const void* p) {
    const unsigned* w = (const unsigned*)p;
    bool hi_zero = true;
#pragma unroll
    for (int k = 0; k < 16; ++k) hi_zero &= (w[2 * k + 1] == 0u);
    if (hi_zero) return 0;
    bool small = true;
#pragma unroll
    for (int k = 0; k < 16; ++k) small &= (w[k] < 0x10000u);
    return small ? 1 : 2;
}

__global__ void detect_kernel(const void* idx, const void* midx) {
    if (threadIdx.x == 0) g_mode[0] = detect_mode(idx);
    if (threadIdx.x == 1) g_mode[1] = detect_mode(midx);
}

__device__ __forceinline__ void load_row3(const void* p, int i, int mode,
                                          int& b, int& y, int& x) {
    if (mode == 0) {
        const long long* q = (const long long*)p + 3 * (size_t)i;
        b = (int)q[0]; y = (int)q[1]; x = (int)q[2];
    } else if (mode == 1) {
        const int* q = (const int*)p + 3 * (size_t)i;
        b = q[0]; y = q[1]; x = q[2];
    } else {
        const float* q = (const float*)p + 3 * (size_t)i;
        b = (int)q[0]; y = (int)q[1]; x = (int)q[2];
    }
    b = b < 0 ? 0 : (b > NB - 1 ? NB - 1 : b);
    y = y < 0 ? 0 : (y > HGT - 1 ? HGT - 1 : y);
    x = x < 0 ? 0 : (x > WID - 1 ? WID - 1 : x);
}

// ---------------------------------------------------------------------------
// Packed f32x2 helpers (sm_103a 2x fp32 path)
// ---------------------------------------------------------------------------
__device__ __forceinline__ unsigned long long fma2(unsigned long long a,
                                                   unsigned long long b,
                                                   unsigned long long c) {
    unsigned long long d;
    asm("fma.rn.f32x2 %0, %1, %2, %3;" : "=l"(d) : "l"(a), "l"(b), "l"(c));
    return d;
}
__device__ __forceinline__ unsigned long long splat2(float a) {
    unsigned long long d;
    unsigned int ai = __float_as_uint(a);
    asm("mov.b64 %0, {%1, %2};" : "=l"(d) : "r"(ai), "r"(ai));
    return d;
}

// ---------------------------------------------------------------------------
// Kernel 1: zero the dense accumulator (d_out) and the mask grid.
// ---------------------------------------------------------------------------
__global__ void zero_kernel(float4* __restrict__ out4, int n_out4) {
    int i = blockIdx.x * blockDim.x + threadIdx.x;
    float4 z = make_float4(0.f, 0.f, 0.f, 0.f);
    if (i < n_out4) out4[i] = z;
    const int n_mask4 = NB * HGT * WID / 4;
    if (i < n_mask4) reinterpret_cast<float4*>(g_mask)[i] = z;
}

// ---------------------------------------------------------------------------
// Kernel 2: scatter mask_values into the mask grid.
// ---------------------------------------------------------------------------
__global__ void mask_scatter_kernel(const void* __restrict__ mi,
                                    const float* __restrict__ mv) {
    int i = blockIdx.x * blockDim.x + threadIdx.x;
    if (i < NMASK) {
        int b, y, x;
        load_row3(mi, i, g_mode[1], b, y, x);
        atomicAdd(&g_mask[(b * HGT + y) * WID + x], mv[i]);
    }
}

// ---------------------------------------------------------------------------
// Kernel 3: fused per-tap GEMM (128 points x 64 out, K=64) + vector-red
// scatter. 256 threads = 16x16; thread (ty,tx) owns 8 rows x 4 cols.
// A tile stored k-major (padded row of 132 floats keeps float4 alignment and
// limits transpose-store bank conflicts to 8-way, paid once per block).
// Mainloop per k: 2 LDS.128 (A) + 1 LDS.128 (B, reinterpreted as 2 packed
// f32x2 operands) + 8 splats + 16 FFMA2  (~27 issues vs 41 scalar).
// ---------------------------------------------------------------------------
__global__ __launch_bounds__(256, 2) void conv_scatter_kernel(
    const float* __restrict__ values, const float* __restrict__ kern,
    const void* __restrict__ idx, float* __restrict__ dense) {
    __shared__ float As[64][132];   // k-major values tile (+4 pad), ~33 KB
    __shared__ float Bs[64][64];    // one tap's 64x64 kernel slice, 16 KB
    __shared__ int Pb[128], Py[128], Px[128];

    const int tid = threadIdx.x;
    const int m0 = blockIdx.x * 128;
    const int mode = g_mode[0];

    // Stage A tile transposed: coalesced float4 gmem reads, scalar smem stores.
    for (int i = tid; i < 128 * 16; i += 256) {
        int m = i >> 4;
        int c = (i & 15) << 2;
        float4 v = *reinterpret_cast<const float4*>(values + (size_t)(m0 + m) * NCH + c);
        As[c + 0][m] = v.x;
        As[c + 1][m] = v.y;
        As[c + 2][m] = v.z;
        As[c + 3][m] = v.w;
    }
    for (int i = tid; i < 128; i += 256) {
        int b, y, x;
        load_row3(idx, m0 + i, mode, b, y, x);
        Pb[i] = b; Py[i] = y; Px[i] = x;
    }

    const int ty = tid >> 4;   // 0..15 -> 8 rows each
    const int tx = tid & 15;   // 0..15 -> 4 cols each

#pragma unroll 1
    for (int tap = 0; tap < 9; ++tap) {
        __syncthreads();
        const float4* bsrc = reinterpret_cast<const float4*>(kern + (size_t)tap * NCH * NCH);
        for (int i = tid; i < 64 * 16; i += 256)
            reinterpret_cast<float4*>(Bs)[i] = bsrc[i];
        __syncthreads();

        unsigned long long c01[8], c23[8];
#pragma unroll
        for (int i = 0; i < 8; ++i) { c01[i] = 0ull; c23[i] = 0ull; }

#pragma unroll 8
        for (int k = 0; k < 64; ++k) {
            // B: one LDS.128; halves are already the packed {b0,b1},{b2,b3}.
            ulonglong2 bb = *reinterpret_cast<const ulonglong2*>(&Bs[k][tx * 4]);
            // A: two LDS.128 covering this thread's 8 rows.
            float4 a0 = *reinterpret_cast<const float4*>(&As[k][ty * 8]);
            float4 a1 = *reinterpret_cast<const float4*>(&As[k][ty * 8 + 4]);
            unsigned long long s0 = splat2(a0.x), s1 = splat2(a0.y);
            unsigned long long s2 = splat2(a0.z), s3 = splat2(a0.w);
            unsigned long long s4 = splat2(a1.x), s5 = splat2(a1.y);
            unsigned long long s6 = splat2(a1.z), s7 = splat2(a1.w);
            c01[0] = fma2(s0, bb.x, c01[0]); c23[0] = fma2(s0, bb.y, c23[0]);
            c01[1] = fma2(s1, bb.x, c01[1]); c23[1] = fma2(s1, bb.y, c23[1]);
            c01[2] = fma2(s2, bb.x, c01[2]); c23[2] = fma2(s2, bb.y, c23[2]);
            c01[3] = fma2(s3, bb.x, c01[3]); c23[3] = fma2(s3, bb.y, c23[3]);
            c01[4] = fma2(s4, bb.x, c01[4]); c23[4] = fma2(s4, bb.y, c23[4]);
            c01[5] = fma2(s5, bb.x, c01[5]); c23[5] = fma2(s5, bb.y, c23[5]);
            c01[6] = fma2(s6, bb.x, c01[6]); c23[6] = fma2(s6, bb.y, c23[6]);
            c01[7] = fma2(s7, bb.x, c01[7]); c23[7] = fma2(s7, bb.y, c23[7]);
        }

        const int dy = tap / 3 - 1;
        const int dx = tap % 3 - 1;
#pragma unroll
        for (int i = 0; i < 8; ++i) {
            int m = ty * 8 + i;
            int sy = Py[m] + dy;
            sy = sy < 0 ? 0 : (sy > HGT - 1 ? HGT - 1 : sy);
            int sx = Px[m] + dx;
            sx = sx < 0 ? 0 : (sx > WID - 1 ? WID - 1 : sx);
            float* p = dense + ((((size_t)Pb[m] * HGT + sy) * WID + sx) * NCH) + tx * 4;
            float f0 = __uint_as_float((unsigned int)c01[i]);
            float f1 = __uint_as_float((unsigned int)(c01[i] >> 32));
            float f2 = __uint_as_float((unsigned int)c23[i]);
            float f3 = __uint_as_float((unsigned int)(c23[i] >> 32));
            asm volatile("red.global.add.v4.f32 [%0], {%1, %2, %3, %4};"
                         :: "l"(p), "f"(f0), "f"(f1), "f"(f2), "f"(f3)
                         : "memory");
        }
    }
}

// ---------------------------------------------------------------------------
// Kernel 4: epilogue  out = (dense + mask*bias) * mask   (in place on d_out)
// ---------------------------------------------------------------------------
__global__ void epilogue_kernel(float4* __restrict__ out4,
                                const float4* __restrict__ bias4) {
    int i = blockIdx.x * blockDim.x + threadIdx.x;
    float m = g_mask[i >> 4];
    float4 d = out4[i];
    float4 bv = __ldg(&bias4[i & 15]);
    d.x = (d.x + m * bv.x) * m;
    d.y = (d.y + m * bv.y) * m;
    d.z = (d.z + m * bv.z) * m;
    d.w = (d.w + m * bv.w) * m;
    out4[i] = d;
}

// ---------------------------------------------------------------------------
extern "C" void kernel_launch(void* const* d_in, const int* in_sizes, int n_in,
                              void* d_out, int out_size) {
    const float* values = nullptr;
    const float* kern = nullptr;
    const float* bias = nullptr;
    const float* mask_values = nullptr;
    const void* indices = nullptr;
    const void* mask_indices = nullptr;

    for (int i = 0; i < n_in; ++i) {
        int s = in_sizes[i];
        if (s == 8388608)      values = (const float*)d_in[i];
        else if (s == 36864)   kern = (const float*)d_in[i];
        else if (s == 64)      bias = (const float*)d_in[i];
        else if (s == 131072)  mask_values = (const float*)d_in[i];
        else if (s == 393216 || s == 786432) {
            if (!indices) indices = d_in[i];
            else          mask_indices = d_in[i];
        }
    }
    if (!values)       values       = (const float*)d_in[0];
    if (!kern)         kern         = (const float*)d_in[1];
    if (!bias)         bias         = (const float*)d_in[2];
    if (!mask_values)  mask_values  = (const float*)d_in[3];
    if (!indices)      indices      = d_in[4];
    if (!mask_indices) mask_indices = d_in[5];

    float* out = (float*)d_out;
    const int n_out4 = NB * HGT * WID * NCH / 4;  // 8388608

    detect_kernel<<<1, 32>>>(indices, mask_indices);
    zero_kernel<<<(n_out4 + 255) / 256, 256>>>((float4*)out, n_out4);
    mask_scatter_kernel<<<(NMASK + 255) / 256, 256>>>(mask_indices, mask_values);
    conv_scatter_kernel<<<NPTS / 128, 256>>>(values, kern, indices, out);
    epilogue_kernel<<<n_out4 / 256, 256>>>((float4*)out, (const float4*)bias);
}

// round 7
// speedup vs baseline: 1.6120x; 1.0305x over previous
#include <cuda_runtime.h>
#include <cstdint>

#define HGT 512
#define WID 512
#define NB 2
#define NCH 64
#define NPTS 131072
#define NMASK 131072

// Scratch via __device__ globals (allocations are forbidden).
__device__ __align__(16) float g_mask[NB * HGT * WID];
__device__ int g_mode[2];   // 0 = int64 rows, 1 = int32 rows, 2 = float32 rows

// ---------------------------------------------------------------------------
// Index-format detection + robust row loader
// ---------------------------------------------------------------------------
__device__ __forceinline__ int detect_mode(const void* p) {
    const unsigned* w = (const unsigned*)p;
    bool hi_zero = true;
#pragma unroll
    for (int k = 0; k < 16; ++k) hi_zero &= (w[2 * k + 1] == 0u);
    if (hi_zero) return 0;
    bool small = true;
#pragma unroll
    for (int k = 0; k < 16; ++k) small &= (w[k] < 0x10000u);
    return small ? 1 : 2;
}

__global__ void detect_kernel(const void* idx, const void* midx) {
    if (threadIdx.x == 0) g_mode[0] = detect_mode(idx);
    if (threadIdx.x == 1) g_mode[1] = detect_mode(midx);
}

__device__ __forceinline__ void load_row3(const void* p, int i, int mode,
                                          int& b, int& y, int& x) {
    if (mode == 0) {
        const long long* q = (const long long*)p + 3 * (size_t)i;
        b = (int)q[0]; y = (int)q[1]; x = (int)q[2];
    } else if (mode == 1) {
        const int* q = (const int*)p + 3 * (size_t)i;
        b = q[0]; y = q[1]; x = q[2];
    } else {
        const float* q = (const float*)p + 3 * (size_t)i;
        b = (int)q[0]; y = (int)q[1]; x = (int)q[2];
    }
    b = b < 0 ? 0 : (b > NB - 1 ? NB - 1 : b);
    y = y < 0 ? 0 : (y > HGT - 1 ? HGT - 1 : y);
    x = x < 0 ? 0 : (x > WID - 1 ? WID - 1 : x);
}

// ---------------------------------------------------------------------------
// Packed f32x2 helpers (sm_103a 2x fp32 path)
// ---------------------------------------------------------------------------
__device__ __forceinline__ unsigned long long fma2(unsigned long long a,
                                                   unsigned long long b,
                                                   unsigned long long c) {
    unsigned long long d;
    asm("fma.rn.f32x2 %0, %1, %2, %3;" : "=l"(d) : "l"(a), "l"(b), "l"(c));
    return d;
}
__device__ __forceinline__ unsigned long long splat2(float a) {
    unsigned long long d;
    unsigned int ai = __float_as_uint(a);
    asm("mov.b64 %0, {%1, %2};" : "=l"(d) : "r"(ai), "r"(ai));
    return d;
}

// ---------------------------------------------------------------------------
// Kernel 1: zero the dense accumulator (d_out) and the mask grid.
// ---------------------------------------------------------------------------
__global__ void zero_kernel(float4* __restrict__ out4, int n_out4) {
    int i = blockIdx.x * blockDim.x + threadIdx.x;
    float4 z = make_float4(0.f, 0.f, 0.f, 0.f);
    if (i < n_out4) out4[i] = z;
    const int n_mask4 = NB * HGT * WID / 4;
    if (i < n_mask4) reinterpret_cast<float4*>(g_mask)[i] = z;
}

// ---------------------------------------------------------------------------
// Kernel 2: scatter mask_values into the mask grid.
// ---------------------------------------------------------------------------
__global__ void mask_scatter_kernel(const void* __restrict__ mi,
                                    const float* __restrict__ mv) {
    int i = blockIdx.x * blockDim.x + threadIdx.x;
    if (i < NMASK) {
        int b, y, x;
        load_row3(mi, i, g_mode[1], b, y, x);
        atomicAdd(&g_mask[(b * HGT + y) * WID + x], mv[i]);
    }
}

// ---------------------------------------------------------------------------
// Kernel 3: fused per-tap GEMM (128 points x 64 out, K=64) + vector-red
// scatter. 256 threads = 16x16; thread (ty,tx) owns 8 rows x 4 cols.
//
// M-pair packing: A is k-major in smem, so As[k][ty*8..+7] loads as 4
// pre-packed f32x2 m-pairs (2x LDS.128, no splats). Only B's 4 channel
// values get splatted. Per-k issues: 2 LDS(A) + 1 LDS(B) + 4 splat +
// 16 FFMA2 = 23 (was 27). acc[mp][n] holds {m=2mp, m=2mp+1} per lane-pair.
// ---------------------------------------------------------------------------
__global__ __launch_bounds__(256, 3) void conv_scatter_kernel(
    const float* __restrict__ values, const float* __restrict__ kern,
    const void* __restrict__ idx, float* __restrict__ dense) {
    __shared__ float As[64][132];   // k-major values tile (+4 pad), ~33 KB
    __shared__ float Bs[64][64];    // one tap's 64x64 kernel slice, 16 KB
    __shared__ int Pb[128], Py[128], Px[128];

    const int tid = threadIdx.x;
    const int m0 = blockIdx.x * 128;
    const int mode = g_mode[0];

    // Point coords first so their LDGs overlap the A staging below.
    for (int i = tid; i < 128; i += 256) {
        int b, y, x;
        load_row3(idx, m0 + i, mode, b, y, x);
        Pb[i] = b; Py[i] = y; Px[i] = x;
    }
    // Stage A transposed: coalesced float4 gmem reads, scalar smem stores.
    for (int i = tid; i < 128 * 16; i += 256) {
        int m = i >> 4;
        int c = (i & 15) << 2;
        float4 v = *reinterpret_cast<const float4*>(values + (size_t)(m0 + m) * NCH + c);
        As[c + 0][m] = v.x;
        As[c + 1][m] = v.y;
        As[c + 2][m] = v.z;
        As[c + 3][m] = v.w;
    }

    const int ty = tid >> 4;   // 0..15 -> 8 consecutive m-rows each
    const int tx = tid & 15;   // 0..15 -> 4 channels each

#pragma unroll 1
    for (int tap = 0; tap < 9; ++tap) {
        __syncthreads();
        const float4* bsrc = reinterpret_cast<const float4*>(kern + (size_t)tap * NCH * NCH);
        for (int i = tid; i < 64 * 16; i += 256)
            reinterpret_cast<float4*>(Bs)[i] = bsrc[i];
        __syncthreads();

        unsigned long long acc[4][4];   // [m-pair][channel]
#pragma unroll
        for (int mp = 0; mp < 4; ++mp)
#pragma unroll
            for (int n = 0; n < 4; ++n) acc[mp][n] = 0ull;

#pragma unroll 8
        for (int k = 0; k < 64; ++k) {
            // A: 8 consecutive m values as 4 pre-packed f32x2 pairs.
            ulonglong2 A0 = *reinterpret_cast<const ulonglong2*>(&As[k][ty * 8]);
            ulonglong2 A1 = *reinterpret_cast<const ulonglong2*>(&As[k][ty * 8 + 4]);
            // B: one LDS.128, then 4 channel splats.
            float4 b = *reinterpret_cast<const float4*>(&Bs[k][tx * 4]);
            unsigned long long sb0 = splat2(b.x), sb1 = splat2(b.y);
            unsigned long long sb2 = splat2(b.z), sb3 = splat2(b.w);
            acc[0][0] = fma2(A0.x, sb0, acc[0][0]);
            acc[0][1] = fma2(A0.x, sb1, acc[0][1]);
            acc[0][2] = fma2(A0.x, sb2, acc[0][2]);
            acc[0][3] = fma2(A0.x, sb3, acc[0][3]);
            acc[1][0] = fma2(A0.y, sb0, acc[1][0]);
            acc[1][1] = fma2(A0.y, sb1, acc[1][1]);
            acc[1][2] = fma2(A0.y, sb2, acc[1][2]);
            acc[1][3] = fma2(A0.y, sb3, acc[1][3]);
            acc[2][0] = fma2(A1.x, sb0, acc[2][0]);
            acc[2][1] = fma2(A1.x, sb1, acc[2][1]);
            acc[2][2] = fma2(A1.x, sb2, acc[2][2]);
            acc[2][3] = fma2(A1.x, sb3, acc[2][3]);
            acc[3][0] = fma2(A1.y, sb0, acc[3][0]);
            acc[3][1] = fma2(A1.y, sb1, acc[3][1]);
            acc[3][2] = fma2(A1.y, sb2, acc[3][2]);
            acc[3][3] = fma2(A1.y, sb3, acc[3][3]);
        }

        const int dy = tap / 3 - 1;
        const int dx = tap % 3 - 1;
#pragma unroll
        for (int mp = 0; mp < 4; ++mp) {
#pragma unroll
            for (int e = 0; e < 2; ++e) {
                int m = ty * 8 + mp * 2 + e;
                int sy = Py[m] + dy;
                sy = sy < 0 ? 0 : (sy > HGT - 1 ? HGT - 1 : sy);
                int sx = Px[m] + dx;
                sx = sx < 0 ? 0 : (sx > WID - 1 ? WID - 1 : sx);
                float* p = dense + ((((size_t)Pb[m] * HGT + sy) * WID + sx) * NCH) + tx * 4;
                float f0, f1, f2, f3;
                if (e == 0) {
                    f0 = __uint_as_float((unsigned int)acc[mp][0]);
                    f1 = __uint_as_float((unsigned int)acc[mp][1]);
                    f2 = __uint_as_float((unsigned int)acc[mp][2]);
                    f3 = __uint_as_float((unsigned int)acc[mp][3]);
                } else {
                    f0 = __uint_as_float((unsigned int)(acc[mp][0] >> 32));
                    f1 = __uint_as_float((unsigned int)(acc[mp][1] >> 32));
                    f2 = __uint_as_float((unsigned int)(acc[mp][2] >> 32));
                    f3 = __uint_as_float((unsigned int)(acc[mp][3] >> 32));
                }
                asm volatile("red.global.add.v4.f32 [%0], {%1, %2, %3, %4};"
                             :: "l"(p), "f"(f0), "f"(f1), "f"(f2), "f"(f3)
                             : "memory");
            }
        }
    }
}

// ---------------------------------------------------------------------------
// Kernel 4: epilogue  out = (dense + mask*bias) * mask   (in place on d_out)
// ---------------------------------------------------------------------------
__global__ void epilogue_kernel(float4* __restrict__ out4,
                                const float4* __restrict__ bias4) {
    int i = blockIdx.x * blockDim.x + threadIdx.x;
    float m = g_mask[i >> 4];
    float4 d = out4[i];
    float4 bv = __ldg(&bias4[i & 15]);
    d.x = (d.x + m * bv.x) * m;
    d.y = (d.y + m * bv.y) * m;
    d.z = (d.z + m * bv.z) * m;
    d.w = (d.w + m * bv.w) * m;
    out4[i] = d;
}

// ---------------------------------------------------------------------------
extern "C" void kernel_launch(void* const* d_in, const int* in_sizes, int n_in,
                              void* d_out, int out_size) {
    const float* values = nullptr;
    const float* kern = nullptr;
    const float* bias = nullptr;
    const float* mask_values = nullptr;
    const void* indices = nullptr;
    const void* mask_indices = nullptr;

    for (int i = 0; i < n_in; ++i) {
        int s = in_sizes[i];
        if (s == 8388608)      values = (const float*)d_in[i];
        else if (s == 36864)   kern = (const float*)d_in[i];
        else if (s == 64)      bias = (const float*)d_in[i];
        else if (s == 131072)  mask_values = (const float*)d_in[i];
        else if (s == 393216 || s == 786432) {
            if (!indices) indices = d_in[i];
            else          mask_indices = d_in[i];
        }
    }
    if (!values)       values       = (const float*)d_in[0];
    if (!kern)         kern         = (const float*)d_in[1];
    if (!bias)         bias         = (const float*)d_in[2];
    if (!mask_values)  mask_values  = (const float*)d_in[3];
    if (!indices)      indices      = d_in[4];
    if (!mask_indices) mask_indices = d_in[5];

    float* out = (float*)d_out;
    const int n_out4 = NB * HGT * WID * NCH / 4;  // 8388608

    detect_kernel<<<1, 32>>>(indices, mask_indices);
    zero_kernel<<<(n_out4 + 255) / 256, 256>>>((float4*)out, n_out4);
    mask_scatter_kernel<<<(NMASK + 255) / 256, 256>>>(mask_indices, mask_values);
    conv_scatter_kernel<<<NPTS / 128, 256>>>(values, kern, indices, out);
    epilogue_kernel<<<n_out4 / 256, 256>>>((float4*)out, (const float4*)bias);
}